// round 12
// baseline (speedup 1.0000x reference)
#include <cuda_runtime.h>

// Inverse Haar transform, fused:
//   out = sum_band upfirdn2d(band, f_band, up=2 bilinear, pad=(1,0,1,0))
// Input  x: (16, 12, 512, 512) f32  -> bands ll/lh/hl/hh = channels [0:3),[3:6),[6:9),[9:12)
// Output  : (16,  3, 1024, 1024) f32
//
// Separable polyphase formulation. s = 1/sqrt(2). Per band = rowFilter (x) colFilter:
//   LL: row l=[s,s],  col l
//   LH: row [s,-s],   col l
//   HL: row l,        col [s,-s]
//   HH: row [s,-s],   col [s,-s]   (outer(h,h) == outer(-h,-h), signs cancel)
//
// Column stage produces UNSCALED streams (scale sigma deferred into row constants):
//   L  col: even h = x[k-1]+x[k]                       (sigma_e = s)
//           odd  h = 0.25(x[k-1]+x[k+1]) + 1.5 x[k]    (sigma_o = s)
//   Hn col: even h = x[k-1]-x[k]                       (sigma_e = 0.5 s)
//           odd  h = x[k-1]-x[k+1]                     (sigma_o = 0.25 s)
// Zero-pad boundary (output row/col 0) handled by per-thread coefficient selection.
// Edge clamp (bilinear resize renormalization) handled by clamped smem halo loads.

__global__ __launch_bounds__(256, 4)
void ihaar_kernel(const float* __restrict__ x, float* __restrict__ out)
{
    __shared__ float sm[4][18][36];   // 4 bands, rows k0-1..k0+16, cols c0-1..c0+34

    const int tx = threadIdx.x;       // 0..15 (2 input cells each -> 4 output cols)
    const int ty = threadIdx.y;       // 0..15 (1 input row -> 2 output rows)
    const int tid = ty * 16 + tx;
    const int c0 = blockIdx.x * 32;   // input col base of this block's cells
    const int k0 = blockIdx.y * 16;   // input row base
    const int plane = blockIdx.z;     // b*3 + c
    const int b = plane / 3;
    const int c = plane - 3 * b;

    // ---------------- stage input tiles (with clamped halo) ----------------
    const float* xb = x + (size_t)(b * 12 + c) * (512 * 512);
    for (int idx = tid; idx < 4 * 18 * 36; idx += 256) {
        int j    = idx % 36;
        int t    = idx / 36;
        int i    = t % 18;
        int band = t / 18;
        int gr = k0 - 1 + i; gr = max(0, min(gr, 511));
        int gc = c0 - 1 + j; gc = max(0, min(gc, 511));
        sm[band][i][j] = xb[(size_t)band * (3 * 512 * 512) + gr * 512 + gc];
    }
    __syncthreads();

    const bool firstcol = (c0 == 0) && (tx == 0);   // output col 0 in this thread
    const bool firstrow = (k0 == 0) && (ty == 0);   // output row 0 in this thread

    // Column-stage even-parity coefficients (only stream d=0 can hit the pad).
    const float la0 = firstcol ? 0.0f : 1.0f;       // L col:  interior (1,1), first (0,1)
    const float la1 = 1.0f;
    const float ha0 = firstcol ? 0.0f : 1.0f;       // Hn col: interior (1,-1), first (0,-2)
    const float ha1 = firstcol ? -2.0f : -1.0f;

    // Row-stage "top" (even output row) coefficients, scale sigma included.
    float llr0 = 0.5f,    llr1 = 0.5f;
    float lhr0 = 0.25f,   lhr1 = -0.25f;
    float hlr0e = 0.25f,  hlr1e = 0.25f,   hlr0o = 0.125f,  hlr1o = 0.125f;
    float hhr0e = 0.125f, hhr1e = -0.125f, hhr0o = 0.0625f, hhr1o = -0.0625f;
    if (firstrow) {
        llr0 = 0.0f;  llr1 = 0.5f;
        lhr0 = 0.0f;  lhr1 = -0.5f;
        hlr0e = 0.0f; hlr1e = 0.25f;  hlr0o = 0.0f; hlr1o = 0.125f;
        hhr0e = 0.0f; hhr1e = -0.25f; hhr0o = 0.0f; hhr1o = -0.125f;
    }

    float aT[4] = {0.f, 0.f, 0.f, 0.f};   // output row 2k   (cols ocol..ocol+3)
    float aB[4] = {0.f, 0.f, 0.f, 0.f};   // output row 2k+1

    // ---------------- band LL (0): col L, row L ----------------
    {
        float h[3][4];
        #pragma unroll
        for (int r = 0; r < 3; r++) {
            const float2* row = (const float2*)&sm[0][ty + r][0];
            float2 p0 = row[tx];
            float2 p1 = row[tx + 1];
            float x0 = p0.x, x1 = p0.y, x2 = p1.x, x3 = p1.y;
            h[r][0] = la0 * x0 + la1 * x1;
            h[r][1] = fmaf(0.25f, x0 + x2, 1.5f * x1);
            h[r][2] = x1 + x2;
            h[r][3] = fmaf(0.25f, x1 + x3, 1.5f * x2);
        }
        #pragma unroll
        for (int d = 0; d < 4; d++) {
            aT[d] = fmaf(llr0, h[0][d], fmaf(llr1, h[1][d], aT[d]));
            aB[d] = fmaf(0.125f, h[0][d] + h[2][d], fmaf(0.75f, h[1][d], aB[d]));
        }
    }

    // ---------------- band LH (1): col L, row [s,-s] ----------------
    {
        float h[3][4];
        #pragma unroll
        for (int r = 0; r < 3; r++) {
            const float2* row = (const float2*)&sm[1][ty + r][0];
            float2 p0 = row[tx];
            float2 p1 = row[tx + 1];
            float x0 = p0.x, x1 = p0.y, x2 = p1.x, x3 = p1.y;
            h[r][0] = la0 * x0 + la1 * x1;
            h[r][1] = fmaf(0.25f, x0 + x2, 1.5f * x1);
            h[r][2] = x1 + x2;
            h[r][3] = fmaf(0.25f, x1 + x3, 1.5f * x2);
        }
        #pragma unroll
        for (int d = 0; d < 4; d++) {
            aT[d] = fmaf(lhr0, h[0][d], fmaf(lhr1, h[1][d], aT[d]));
            aB[d] = fmaf(0.125f, h[0][d] - h[2][d], aB[d]);
        }
    }

    // ---------------- band HL (2): col [s,-s], row L ----------------
    {
        float h[3][4];
        #pragma unroll
        for (int r = 0; r < 3; r++) {
            const float2* row = (const float2*)&sm[2][ty + r][0];
            float2 p0 = row[tx];
            float2 p1 = row[tx + 1];
            float x0 = p0.x, x1 = p0.y, x2 = p1.x, x3 = p1.y;
            h[r][0] = ha0 * x0 + ha1 * x1;
            h[r][1] = x0 - x2;
            h[r][2] = x1 - x2;
            h[r][3] = x1 - x3;
        }
        // even col streams d=0,2 use sigma_e, odd d=1,3 use sigma_o
        aT[0] = fmaf(hlr0e, h[0][0], fmaf(hlr1e, h[1][0], aT[0]));
        aT[1] = fmaf(hlr0o, h[0][1], fmaf(hlr1o, h[1][1], aT[1]));
        aT[2] = fmaf(hlr0e, h[0][2], fmaf(hlr1e, h[1][2], aT[2]));
        aT[3] = fmaf(hlr0o, h[0][3], fmaf(hlr1o, h[1][3], aT[3]));
        aB[0] = fmaf(0.0625f,  h[0][0] + h[2][0], fmaf(0.375f,  h[1][0], aB[0]));
        aB[1] = fmaf(0.03125f, h[0][1] + h[2][1], fmaf(0.1875f, h[1][1], aB[1]));
        aB[2] = fmaf(0.0625f,  h[0][2] + h[2][2], fmaf(0.375f,  h[1][2], aB[2]));
        aB[3] = fmaf(0.03125f, h[0][3] + h[2][3], fmaf(0.1875f, h[1][3], aB[3]));
    }

    // ---------------- band HH (3): col [s,-s], row [s,-s] --------------
    {
        float h[3][4];
        #pragma unroll
        for (int r = 0; r < 3; r++) {
            const float2* row = (const float2*)&sm[3][ty + r][0];
            float2 p0 = row[tx];
            float2 p1 = row[tx + 1];
            float x0 = p0.x, x1 = p0.y, x2 = p1.x, x3 = p1.y;
            h[r][0] = ha0 * x0 + ha1 * x1;
            h[r][1] = x0 - x2;
            h[r][2] = x1 - x2;
            h[r][3] = x1 - x3;
        }
        aT[0] = fmaf(hhr0e, h[0][0], fmaf(hhr1e, h[1][0], aT[0]));
        aT[1] = fmaf(hhr0o, h[0][1], fmaf(hhr1o, h[1][1], aT[1]));
        aT[2] = fmaf(hhr0e, h[0][2], fmaf(hhr1e, h[1][2], aT[2]));
        aT[3] = fmaf(hhr0o, h[0][3], fmaf(hhr1o, h[1][3], aT[3]));
        aB[0] = fmaf(0.0625f,  h[0][0] - h[2][0], aB[0]);
        aB[1] = fmaf(0.03125f, h[0][1] - h[2][1], aB[1]);
        aB[2] = fmaf(0.0625f,  h[0][2] - h[2][2], aB[2]);
        aB[3] = fmaf(0.03125f, h[0][3] - h[2][3], aB[3]);
    }

    // ---------------- store 2 rows x 4 cols (two STG.128) ----------------
    const int orow = 2 * (k0 + ty);
    const int ocol = 2 * c0 + 4 * tx;
    float* op = out + ((size_t)plane * 1024 + orow) * 1024 + ocol;
    *reinterpret_cast<float4*>(op)        = make_float4(aT[0], aT[1], aT[2], aT[3]);
    *reinterpret_cast<float4*>(op + 1024) = make_float4(aB[0], aB[1], aB[2], aB[3]);
}

extern "C" void kernel_launch(void* const* d_in, const int* in_sizes, int n_in,
                              void* d_out, int out_size)
{
    const float* x = (const float*)d_in[0];
    float* out = (float*)d_out;
    // x: (16,12,512,512); out: (16,3,1024,1024)
    dim3 block(16, 16);
    dim3 grid(512 / 32, 512 / 16, 16 * 3);
    ihaar_kernel<<<grid, block>>>(x, out);
}

// round 15
// speedup vs baseline: 1.5541x; 1.5541x over previous
#include <cuda_runtime.h>

// Inverse Haar transform, fused. See R1-R11 derivation.
// x: (16,12,512,512) f32 -> out: (16,3,1024,1024) f32
// Separable polyphase; column stage unscaled, sigma folded into row constants.
// R13/R14: staging overhaul — float4 fast path for interior-x blocks (measured
// bottleneck was integer ALU in the scalar staging loop: alu=47.6%, dram=25.3%).

__global__ __launch_bounds__(256, 4)
void ihaar_kernel(const float* __restrict__ x, float* __restrict__ out)
{
    __shared__ float sm[4][18][36];   // 4 bands, rows k0-1..k0+16, cols c0-1..c0+34

    const int tx = threadIdx.x;       // 0..15
    const int ty = threadIdx.y;       // 0..15
    const int tid = ty * 16 + tx;
    const int c0 = blockIdx.x * 32;
    const int k0 = blockIdx.y * 16;
    const int plane = blockIdx.z;
    const int b = plane / 3;
    const int c = plane - 3 * b;

    const float* xb = x + (size_t)(b * 12 + c) * (512 * 512);

    // ---------------- stage input tiles ----------------
    const bool xedge = (blockIdx.x == 0) || (blockIdx.x == 15);
    if (!xedge) {
        // FAST PATH: columns c0-4 .. c0+35 all in-bounds -> aligned float4 loads.
        // 72 (band,row) pairs x 10 float4 each = 720 loads; j = gc-(c0-1) = 4k-3+d.
        // Row clamp handles y-boundary blocks (cheap, 2 ops/row).
        #pragma unroll
        for (int it = 0; it < 3; it++) {
            int L = tid + 256 * it;
            if (L < 720) {
                int rowid = L / 10;          // 0..71
                int k     = L - rowid * 10;  // 0..9
                int band  = rowid / 18;      // 0..3
                int i     = rowid - band * 18;
                int gr = k0 - 1 + i; gr = max(0, min(gr, 511));
                const float4* src = reinterpret_cast<const float4*>(
                    xb + (size_t)band * (3 * 512 * 512) + (size_t)gr * 512 + (c0 - 4));
                float4 v = src[k];
                int j = 4 * k - 3;
                float* dst = &sm[band][i][0];
                if (j     >= 0           ) dst[j]     = v.x;   // only k=0 fails
                if (j + 1 >= 0           ) dst[j + 1] = v.y;
                if (j + 2 >= 0           ) dst[j + 2] = v.z;
                if (j + 3 < 36           ) dst[j + 3] = v.w;   // only k=9 fails
            }
        }
    } else {
        // EDGE PATH (blockIdx.x 0 or 15): original scalar loop with full clamps.
        for (int idx = tid; idx < 4 * 18 * 36; idx += 256) {
            int j    = idx % 36;
            int t    = idx / 36;
            int i    = t % 18;
            int band = t / 18;
            int gr = k0 - 1 + i; gr = max(0, min(gr, 511));
            int gc = c0 - 1 + j; gc = max(0, min(gc, 511));
            sm[band][i][j] = xb[(size_t)band * (3 * 512 * 512) + gr * 512 + gc];
        }
    }
    __syncthreads();

    const bool firstcol = (c0 == 0) && (tx == 0);
    const bool firstrow = (k0 == 0) && (ty == 0);

    // Column-stage even-parity coefficients (only stream d=0 can hit the pad).
    const float la0 = firstcol ? 0.0f : 1.0f;
    const float la1 = 1.0f;
    const float ha0 = firstcol ? 0.0f : 1.0f;
    const float ha1 = firstcol ? -2.0f : -1.0f;

    // Row-stage "top" (even output row) coefficients, scale sigma included.
    float llr0 = 0.5f,    llr1 = 0.5f;
    float lhr0 = 0.25f,   lhr1 = -0.25f;
    float hlr0e = 0.25f,  hlr1e = 0.25f,   hlr0o = 0.125f,  hlr1o = 0.125f;
    float hhr0e = 0.125f, hhr1e = -0.125f, hhr0o = 0.0625f, hhr1o = -0.0625f;
    if (firstrow) {
        llr0 = 0.0f;  llr1 = 0.5f;
        lhr0 = 0.0f;  lhr1 = -0.5f;
        hlr0e = 0.0f; hlr1e = 0.25f;  hlr0o = 0.0f; hlr1o = 0.125f;
        hhr0e = 0.0f; hhr1e = -0.25f; hhr0o = 0.0f; hhr1o = -0.125f;
    }

    float aT[4] = {0.f, 0.f, 0.f, 0.f};
    float aB[4] = {0.f, 0.f, 0.f, 0.f};

    // ---------------- band LL (0): col L, row L ----------------
    {
        float h[3][4];
        #pragma unroll
        for (int r = 0; r < 3; r++) {
            const float2* row = (const float2*)&sm[0][ty + r][0];
            float2 p0 = row[tx];
            float2 p1 = row[tx + 1];
            float x0 = p0.x, x1 = p0.y, x2 = p1.x, x3 = p1.y;
            h[r][0] = la0 * x0 + la1 * x1;
            h[r][1] = fmaf(0.25f, x0 + x2, 1.5f * x1);
            h[r][2] = x1 + x2;
            h[r][3] = fmaf(0.25f, x1 + x3, 1.5f * x2);
        }
        #pragma unroll
        for (int d = 0; d < 4; d++) {
            aT[d] = fmaf(llr0, h[0][d], fmaf(llr1, h[1][d], aT[d]));
            aB[d] = fmaf(0.125f, h[0][d] + h[2][d], fmaf(0.75f, h[1][d], aB[d]));
        }
    }

    // ---------------- band LH (1): col L, row [s,-s] ----------------
    {
        float h[3][4];
        #pragma unroll
        for (int r = 0; r < 3; r++) {
            const float2* row = (const float2*)&sm[1][ty + r][0];
            float2 p0 = row[tx];
            float2 p1 = row[tx + 1];
            float x0 = p0.x, x1 = p0.y, x2 = p1.x, x3 = p1.y;
            h[r][0] = la0 * x0 + la1 * x1;
            h[r][1] = fmaf(0.25f, x0 + x2, 1.5f * x1);
            h[r][2] = x1 + x2;
            h[r][3] = fmaf(0.25f, x1 + x3, 1.5f * x2);
        }
        #pragma unroll
        for (int d = 0; d < 4; d++) {
            aT[d] = fmaf(lhr0, h[0][d], fmaf(lhr1, h[1][d], aT[d]));
            aB[d] = fmaf(0.125f, h[0][d] - h[2][d], aB[d]);
        }
    }

    // ---------------- band HL (2): col [s,-s], row L ----------------
    {
        float h[3][4];
        #pragma unroll
        for (int r = 0; r < 3; r++) {
            const float2* row = (const float2*)&sm[2][ty + r][0];
            float2 p0 = row[tx];
            float2 p1 = row[tx + 1];
            float x0 = p0.x, x1 = p0.y, x2 = p1.x, x3 = p1.y;
            h[r][0] = ha0 * x0 + ha1 * x1;
            h[r][1] = x0 - x2;
            h[r][2] = x1 - x2;
            h[r][3] = x1 - x3;
        }
        aT[0] = fmaf(hlr0e, h[0][0], fmaf(hlr1e, h[1][0], aT[0]));
        aT[1] = fmaf(hlr0o, h[0][1], fmaf(hlr1o, h[1][1], aT[1]));
        aT[2] = fmaf(hlr0e, h[0][2], fmaf(hlr1e, h[1][2], aT[2]));
        aT[3] = fmaf(hlr0o, h[0][3], fmaf(hlr1o, h[1][3], aT[3]));
        aB[0] = fmaf(0.0625f,  h[0][0] + h[2][0], fmaf(0.375f,  h[1][0], aB[0]));
        aB[1] = fmaf(0.03125f, h[0][1] + h[2][1], fmaf(0.1875f, h[1][1], aB[1]));
        aB[2] = fmaf(0.0625f,  h[0][2] + h[2][2], fmaf(0.375f,  h[1][2], aB[2]));
        aB[3] = fmaf(0.03125f, h[0][3] + h[2][3], fmaf(0.1875f, h[1][3], aB[3]));
    }

    // ---------------- band HH (3): col [s,-s], row [s,-s] --------------
    {
        float h[3][4];
        #pragma unroll
        for (int r = 0; r < 3; r++) {
            const float2* row = (const float2*)&sm[3][ty + r][0];
            float2 p0 = row[tx];
            float2 p1 = row[tx + 1];
            float x0 = p0.x, x1 = p0.y, x2 = p1.x, x3 = p1.y;
            h[r][0] = ha0 * x0 + ha1 * x1;
            h[r][1] = x0 - x2;
            h[r][2] = x1 - x2;
            h[r][3] = x1 - x3;
        }
        aT[0] = fmaf(hhr0e, h[0][0], fmaf(hhr1e, h[1][0], aT[0]));
        aT[1] = fmaf(hhr0o, h[0][1], fmaf(hhr1o, h[1][1], aT[1]));
        aT[2] = fmaf(hhr0e, h[0][2], fmaf(hhr1e, h[1][2], aT[2]));
        aT[3] = fmaf(hhr0o, h[0][3], fmaf(hhr1o, h[1][3], aT[3]));
        aB[0] = fmaf(0.0625f,  h[0][0] - h[2][0], aB[0]);
        aB[1] = fmaf(0.03125f, h[0][1] - h[2][1], aB[1]);
        aB[2] = fmaf(0.0625f,  h[0][2] - h[2][2], aB[2]);
        aB[3] = fmaf(0.03125f, h[0][3] - h[2][3], aB[3]);
    }

    // ---------------- store 2 rows x 4 cols (two STG.128) ----------------
    const int orow = 2 * (k0 + ty);
    const int ocol = 2 * c0 + 4 * tx;
    float* op = out + ((size_t)plane * 1024 + orow) * 1024 + ocol;
    *reinterpret_cast<float4*>(op)        = make_float4(aT[0], aT[1], aT[2], aT[3]);
    *reinterpret_cast<float4*>(op + 1024) = make_float4(aB[0], aB[1], aB[2], aB[3]);
}

extern "C" void kernel_launch(void* const* d_in, const int* in_sizes, int n_in,
                              void* d_out, int out_size)
{
    const float* x = (const float*)d_in[0];
    float* out = (float*)d_out;
    dim3 block(16, 16);
    dim3 grid(512 / 32, 512 / 16, 16 * 3);
    ihaar_kernel<<<grid, block>>>(x, out);
}